// round 1
// baseline (speedup 1.0000x reference)
#include <cuda_runtime.h>
#include <math.h>

// Problem constants
#define NTOK 4096      // B*S tokens
#define DDIM 1024      // hidden
#define IDIM 4096      // intermediate
#define NEXP 8         // experts
#define TOPK 2

// ---------------------------------------------------------------------------
// Scratch (static device memory -- allocation-free per harness rules)
// ---------------------------------------------------------------------------
__device__ int   g_cnt[NEXP];                               // tokens per expert
__device__ int   g_tok[NEXP * NTOK];                        // token id per (e, slot)
__device__ int   g_prow[NTOK * TOPK];                       // token -> global row (e*NTOK+slot)
__device__ float g_pw[NTOK * TOPK];                         // token -> routing weight
__device__ float g_h[(size_t)NEXP * NTOK * IDIM];           // gelu(x@w1^T+b1)  (512 MB)
__device__ float g_y[(size_t)NEXP * NTOK * DDIM];           // h@w2^T+b2        (128 MB)

// ---------------------------------------------------------------------------
// Kernel 0: zero expert counters
// ---------------------------------------------------------------------------
__global__ void zero_cnt_kernel() {
    if (threadIdx.x < NEXP) g_cnt[threadIdx.x] = 0;
}

// ---------------------------------------------------------------------------
// Kernel 1: routing. One block per token. logits = x @ gate_w^T + gate_b,
// top-2 (first-index tiebreak like jax.lax.top_k), softmax over the 2 values,
// atomic slot assignment into per-expert token lists.
// ---------------------------------------------------------------------------
__global__ void routing_kernel(const float* __restrict__ x,
                               const float* __restrict__ gw,
                               const float* __restrict__ gb) {
    const int n   = blockIdx.x;
    const int tid = threadIdx.x;          // 256 threads
    const float* xr = x + (size_t)n * DDIM;

    float acc[NEXP];
#pragma unroll
    for (int e = 0; e < NEXP; e++) acc[e] = 0.f;

    for (int d = tid; d < DDIM; d += 256) {
        const float xv = xr[d];
#pragma unroll
        for (int e = 0; e < NEXP; e++)
            acc[e] = fmaf(xv, gw[e * DDIM + d], acc[e]);
    }

    __shared__ float s[NEXP][256];
#pragma unroll
    for (int e = 0; e < NEXP; e++) s[e][tid] = acc[e];
    __syncthreads();

    for (int off = 128; off > 0; off >>= 1) {
        if (tid < off) {
#pragma unroll
            for (int e = 0; e < NEXP; e++) s[e][tid] += s[e][tid + off];
        }
        __syncthreads();
    }

    if (tid == 0) {
        float logits[NEXP];
#pragma unroll
        for (int e = 0; e < NEXP; e++) logits[e] = s[e][0] + gb[e];

        // top-1 (strict >, keeps first index on ties)
        int i0 = 0; float v0 = logits[0];
#pragma unroll
        for (int e = 1; e < NEXP; e++)
            if (logits[e] > v0) { v0 = logits[e]; i0 = e; }
        // top-2
        int i1 = -1; float v1 = -INFINITY;
#pragma unroll
        for (int e = 0; e < NEXP; e++)
            if (e != i0 && logits[e] > v1) { v1 = logits[e]; i1 = e; }

        // softmax over [v0, v1] (v0 >= v1)
        const float ew = expf(v1 - v0);
        const float inv = 1.f / (1.f + ew);
        const float w0 = inv;
        const float w1 = ew * inv;

        int idx[2] = { i0, i1 };
        float ww[2] = { w0, w1 };
#pragma unroll
        for (int k = 0; k < TOPK; k++) {
            const int e = idx[k];
            const int slot = atomicAdd(&g_cnt[e], 1);
            const int row = e * NTOK + slot;
            g_tok[row] = n;
            g_prow[n * TOPK + k] = row;
            g_pw[n * TOPK + k] = ww[k];
        }
    }
}

// ---------------------------------------------------------------------------
// Kernel 2/3: tiled fp32 GEMM per expert.
// GATHER=true  : A rows gathered from x via g_tok;  GELU epilogue -> g_h
// GATHER=false : A rows read directly from g_h;     plain bias    -> g_y
// Computes Out[m, n] = act( sum_k A[m,k] * W[e, n, k] + bias[e, n] )
// BM=BN=128, BK=16, 256 threads, 8x8 per-thread microtile.
// ---------------------------------------------------------------------------
template <bool GATHER, bool GELU>
__global__ __launch_bounds__(256, 2)
void sgemm_moe(const float* __restrict__ Ain,     // x (GATHER) else unused
               const float* __restrict__ W,       // [E, Ncols, Kdim]
               const float* __restrict__ bias,    // [E, Ncols]
               int Kdim, int Ncols) {
    const int e = blockIdx.z;
    const int cnt_e = g_cnt[e];
    const int m0 = blockIdx.y * 128;
    if (m0 >= cnt_e) return;
    const int n0 = blockIdx.x * 128;
    const int tid = threadIdx.x;

    const float* A   = GATHER ? Ain : g_h;
    float*       Out = GELU ? g_h : g_y;

    __shared__ float As[16][128];
    __shared__ float Bs[16][128];

    const int lrow = tid >> 2;            // 0..63
    const int lcol = (tid & 3) << 2;      // 0,4,8,12

    // A row pointers for the two rows this thread loads per k-tile
    const float* aptr[2];
    bool avalid[2];
#pragma unroll
    for (int r = 0; r < 2; r++) {
        const int m = m0 + lrow + 64 * r;
        avalid[r] = (m < cnt_e);
        const int row = e * NTOK + m;
        int arow;
        if (GATHER) arow = avalid[r] ? g_tok[row] : 0;
        else        arow = avalid[r] ? row : 0;
        aptr[r] = A + (size_t)arow * Kdim;
    }
    const float* Wbase = W + ((size_t)e * Ncols + n0) * Kdim;

    const int tx = tid & 15;
    const int ty = tid >> 4;

    float c[8][8];
#pragma unroll
    for (int i = 0; i < 8; i++)
#pragma unroll
        for (int j = 0; j < 8; j++) c[i][j] = 0.f;

    float a[8], b[8];

    for (int k0 = 0; k0 < Kdim; k0 += 16) {
        // ---- load A tile (transposed into As[k][m]) ----
#pragma unroll
        for (int r = 0; r < 2; r++) {
            float4 v = make_float4(0.f, 0.f, 0.f, 0.f);
            if (avalid[r])
                v = *reinterpret_cast<const float4*>(aptr[r] + k0 + lcol);
            const int mm = lrow + 64 * r;
            As[lcol + 0][mm] = v.x;
            As[lcol + 1][mm] = v.y;
            As[lcol + 2][mm] = v.z;
            As[lcol + 3][mm] = v.w;
        }
        // ---- load W tile (transposed into Bs[k][n]) ----
#pragma unroll
        for (int r = 0; r < 2; r++) {
            const int nn = lrow + 64 * r;
            const float4 v = *reinterpret_cast<const float4*>(
                Wbase + (size_t)nn * Kdim + k0 + lcol);
            Bs[lcol + 0][nn] = v.x;
            Bs[lcol + 1][nn] = v.y;
            Bs[lcol + 2][nn] = v.z;
            Bs[lcol + 3][nn] = v.w;
        }
        __syncthreads();

#pragma unroll
        for (int kk = 0; kk < 16; kk++) {
            *reinterpret_cast<float4*>(a)     = *reinterpret_cast<const float4*>(&As[kk][ty * 8]);
            *reinterpret_cast<float4*>(a + 4) = *reinterpret_cast<const float4*>(&As[kk][ty * 8 + 4]);
            *reinterpret_cast<float4*>(b)     = *reinterpret_cast<const float4*>(&Bs[kk][tx * 8]);
            *reinterpret_cast<float4*>(b + 4) = *reinterpret_cast<const float4*>(&Bs[kk][tx * 8 + 4]);
#pragma unroll
            for (int i = 0; i < 8; i++)
#pragma unroll
                for (int j = 0; j < 8; j++)
                    c[i][j] = fmaf(a[i], b[j], c[i][j]);
        }
        __syncthreads();
    }

    // ---- epilogue: bias (+ exact GELU), vectorized stores ----
    const float* brow = bias + (size_t)e * Ncols + n0 + tx * 8;
#pragma unroll
    for (int i = 0; i < 8; i++) {
        const int m = m0 + ty * 8 + i;
        if (m >= cnt_e) continue;
        float* orow = Out + ((size_t)(e * NTOK + m)) * Ncols + n0 + tx * 8;
#pragma unroll
        for (int j = 0; j < 8; j += 4) {
            float4 v;
            v.x = c[i][j + 0] + brow[j + 0];
            v.y = c[i][j + 1] + brow[j + 1];
            v.z = c[i][j + 2] + brow[j + 2];
            v.w = c[i][j + 3] + brow[j + 3];
            if (GELU) {
                v.x = 0.5f * v.x * (1.f + erff(v.x * 0.70710678118654752f));
                v.y = 0.5f * v.y * (1.f + erff(v.y * 0.70710678118654752f));
                v.z = 0.5f * v.z * (1.f + erff(v.z * 0.70710678118654752f));
                v.w = 0.5f * v.w * (1.f + erff(v.w * 0.70710678118654752f));
            }
            *reinterpret_cast<float4*>(orow + j) = v;
        }
    }
}

// ---------------------------------------------------------------------------
// Kernel 4: combine. out[n, d] = w0 * y[row0, d] + w1 * y[row1, d]
// ---------------------------------------------------------------------------
__global__ void combine_kernel(float* __restrict__ out) {
    const int idx = blockIdx.x * 256 + threadIdx.x;   // over NTOK*DDIM/4
    const int n = idx >> 8;                           // DDIM/4 = 256 vec4 per token
    const int d = (idx & 255) << 2;
    const float w0 = g_pw[2 * n];
    const float w1 = g_pw[2 * n + 1];
    const int   r0 = g_prow[2 * n];
    const int   r1 = g_prow[2 * n + 1];
    const float4 a = *reinterpret_cast<const float4*>(&g_y[(size_t)r0 * DDIM + d]);
    const float4 b = *reinterpret_cast<const float4*>(&g_y[(size_t)r1 * DDIM + d]);
    float4 o;
    o.x = w0 * a.x + w1 * b.x;
    o.y = w0 * a.y + w1 * b.y;
    o.z = w0 * a.z + w1 * b.z;
    o.w = w0 * a.w + w1 * b.w;
    *reinterpret_cast<float4*>(&out[(size_t)n * DDIM + d]) = o;
}

// ---------------------------------------------------------------------------
// Launch
// ---------------------------------------------------------------------------
extern "C" void kernel_launch(void* const* d_in, const int* in_sizes, int n_in,
                              void* d_out, int out_size) {
    const float* x      = (const float*)d_in[0];   // [B, S, D]
    const float* gate_w = (const float*)d_in[1];   // [E, D]
    const float* gate_b = (const float*)d_in[2];   // [E]
    const float* w1     = (const float*)d_in[3];   // [E, I, D]
    const float* b1     = (const float*)d_in[4];   // [E, I]
    const float* w2     = (const float*)d_in[5];   // [E, D, I]
    const float* b2     = (const float*)d_in[6];   // [E, D]
    float* out = (float*)d_out;                    // [B, S, D]

    zero_cnt_kernel<<<1, 32>>>();
    routing_kernel<<<NTOK, 256>>>(x, gate_w, gate_b);

    // GEMM1: h = gelu(x_gathered @ w1^T + b1)    [rows x IDIM], K = DDIM
    dim3 g1(IDIM / 128, NTOK / 128, NEXP);
    sgemm_moe<true, true><<<g1, 256>>>(x, w1, b1, DDIM, IDIM);

    // GEMM2: y = h @ w2^T + b2                   [rows x DDIM], K = IDIM
    dim3 g2(DDIM / 128, NTOK / 128, NEXP);
    sgemm_moe<false, false><<<g2, 256>>>(nullptr, w2, b2, IDIM, DDIM);

    combine_kernel<<<(NTOK * DDIM / 4) / 256, 256>>>(out);
}

// round 3
// speedup vs baseline: 1.8955x; 1.8955x over previous
#include <cuda_runtime.h>
#include <cuda_bf16.h>
#include <math.h>
#include <stdint.h>

#define NTOK 4096
#define DDIM 1024
#define IDIM 4096
#define NEXP 8
#define ROWCAP 9216           // 8192 assignments + 8*128 padding

// ---------------------------------------------------------------------------
// Static scratch
// ---------------------------------------------------------------------------
__device__ int   g_cnt[NEXP];
__device__ int   g_off[NEXP + 1];
__device__ int   g_tok[NEXP * NTOK];
__device__ int   g_prow[NTOK * 2];
__device__ float g_pw[NTOK * 2];

__device__ __nv_bfloat16 g_xhi[(size_t)ROWCAP * DDIM];
__device__ __nv_bfloat16 g_xlo[(size_t)ROWCAP * DDIM];
__device__ __nv_bfloat16 g_w1hi[(size_t)NEXP * IDIM * DDIM];
__device__ __nv_bfloat16 g_w1lo[(size_t)NEXP * IDIM * DDIM];
__device__ __nv_bfloat16 g_w2hi[(size_t)NEXP * DDIM * IDIM];
__device__ __nv_bfloat16 g_w2lo[(size_t)NEXP * DDIM * IDIM];
__device__ __nv_bfloat16 g_hhi[(size_t)ROWCAP * IDIM];
__device__ __nv_bfloat16 g_hlo[(size_t)ROWCAP * IDIM];
__device__ float g_y[(size_t)ROWCAP * DDIM];

// ---------------------------------------------------------------------------
// Helpers (sm_80-era PTX only: compiles under compute_103 base target)
// ---------------------------------------------------------------------------
__device__ __forceinline__ uint32_t smem_u32(const void* p) {
    uint32_t a;
    asm("{ .reg .u64 t; cvta.to.shared.u64 t, %1; cvt.u32.u64 %0, t; }" : "=r"(a) : "l"(p));
    return a;
}
__device__ __forceinline__ uint32_t swz(uint32_t o) { return o ^ ((o >> 3) & 0x70); }

__device__ __forceinline__ void cp16(uint32_t dst, const void* src) {
    asm volatile("cp.async.cg.shared.global [%0], [%1], 16;\n" :: "r"(dst), "l"(src) : "memory");
}
__device__ __forceinline__ void cp_commit() {
    asm volatile("cp.async.commit_group;\n" ::: "memory");
}
template<int N>
__device__ __forceinline__ void cp_wait() {
    asm volatile("cp.async.wait_group %0;\n" :: "n"(N) : "memory");
}
__device__ __forceinline__ void ldm_x4(uint32_t* r, uint32_t addr) {
    asm volatile("ldmatrix.sync.aligned.m8n8.x4.shared.b16 {%0,%1,%2,%3}, [%4];"
                 : "=r"(r[0]), "=r"(r[1]), "=r"(r[2]), "=r"(r[3]) : "r"(addr));
}
__device__ __forceinline__ void mma_bf16(float* c, const uint32_t* a, const uint32_t* b) {
    asm volatile(
        "mma.sync.aligned.m16n8k16.row.col.f32.bf16.bf16.f32 "
        "{%0,%1,%2,%3}, {%4,%5,%6,%7}, {%8,%9}, {%0,%1,%2,%3};"
        : "+f"(c[0]), "+f"(c[1]), "+f"(c[2]), "+f"(c[3])
        : "r"(a[0]), "r"(a[1]), "r"(a[2]), "r"(a[3]), "r"(b[0]), "r"(b[1]));
}
__device__ __forceinline__ uint32_t pack_bf2(__nv_bfloat16 a, __nv_bfloat16 b) {
    return ((uint32_t)__bfloat16_as_ushort(b) << 16) | (uint32_t)__bfloat16_as_ushort(a);
}

// ---------------------------------------------------------------------------
// Kernel: zero counters
// ---------------------------------------------------------------------------
__global__ void zero_cnt_kernel() {
    if (threadIdx.x < NEXP) g_cnt[threadIdx.x] = 0;
}

// ---------------------------------------------------------------------------
// Kernel: routing (one block per token)
// ---------------------------------------------------------------------------
__global__ void routing_kernel(const float* __restrict__ x,
                               const float* __restrict__ gw,
                               const float* __restrict__ gb) {
    const int n = blockIdx.x;
    const int tid = threadIdx.x;
    const float* xr = x + (size_t)n * DDIM;

    float acc[NEXP];
#pragma unroll
    for (int e = 0; e < NEXP; e++) acc[e] = 0.f;
    for (int d = tid; d < DDIM; d += 256) {
        const float xv = xr[d];
#pragma unroll
        for (int e = 0; e < NEXP; e++)
            acc[e] = fmaf(xv, gw[e * DDIM + d], acc[e]);
    }
    __shared__ float s[NEXP][256];
#pragma unroll
    for (int e = 0; e < NEXP; e++) s[e][tid] = acc[e];
    __syncthreads();
    for (int off = 128; off > 0; off >>= 1) {
        if (tid < off) {
#pragma unroll
            for (int e = 0; e < NEXP; e++) s[e][tid] += s[e][tid + off];
        }
        __syncthreads();
    }
    if (tid == 0) {
        float logits[NEXP];
#pragma unroll
        for (int e = 0; e < NEXP; e++) logits[e] = s[e][0] + gb[e];
        int i0 = 0; float v0 = logits[0];
#pragma unroll
        for (int e = 1; e < NEXP; e++)
            if (logits[e] > v0) { v0 = logits[e]; i0 = e; }
        int i1 = -1; float v1 = -INFINITY;
#pragma unroll
        for (int e = 0; e < NEXP; e++)
            if (e != i0 && logits[e] > v1) { v1 = logits[e]; i1 = e; }
        const float ew = expf(v1 - v0);
        const float inv = 1.f / (1.f + ew);
        int idx[2] = { i0, i1 };
        float ww[2] = { inv, ew * inv };
#pragma unroll
        for (int k = 0; k < 2; k++) {
            const int e = idx[k];
            const int slot = atomicAdd(&g_cnt[e], 1);
            g_tok[e * NTOK + slot] = n;
            g_prow[n * 2 + k] = e * NTOK + slot;
            g_pw[n * 2 + k] = ww[k];
        }
    }
}

// ---------------------------------------------------------------------------
// Kernel: 128-aligned exclusive prefix of counts
// ---------------------------------------------------------------------------
__global__ void offsets_kernel() {
    if (threadIdx.x == 0) {
        int o = 0;
        for (int e = 0; e < NEXP; e++) {
            g_off[e] = o;
            o += (g_cnt[e] + 127) & ~127;
        }
        g_off[NEXP] = o;
    }
}

// ---------------------------------------------------------------------------
// Kernel: gather token rows into compacted layout, split fp32 -> bf16 hi/lo
// ---------------------------------------------------------------------------
__global__ void gather_x_kernel(const float* __restrict__ x) {
    const int row = blockIdx.x;
    const int tid = threadIdx.x;
    int e = -1, slot = 0;
#pragma unroll
    for (int i = 0; i < NEXP; i++) {
        if (row >= g_off[i] && row < g_off[i + 1]) { e = i; slot = row - g_off[i]; }
    }
    const bool valid = (e >= 0) && (slot < g_cnt[e]);
    uint2* dh = reinterpret_cast<uint2*>(g_xhi + (size_t)row * DDIM);
    uint2* dl = reinterpret_cast<uint2*>(g_xlo + (size_t)row * DDIM);
    if (valid) {
        const int token = g_tok[e * NTOK + slot];
        const float4* src = reinterpret_cast<const float4*>(x + (size_t)token * DDIM);
        float4 v = src[tid];
        __nv_bfloat16 h0 = __float2bfloat16(v.x), h1 = __float2bfloat16(v.y);
        __nv_bfloat16 h2 = __float2bfloat16(v.z), h3 = __float2bfloat16(v.w);
        __nv_bfloat16 l0 = __float2bfloat16(v.x - __bfloat162float(h0));
        __nv_bfloat16 l1 = __float2bfloat16(v.y - __bfloat162float(h1));
        __nv_bfloat16 l2 = __float2bfloat16(v.z - __bfloat162float(h2));
        __nv_bfloat16 l3 = __float2bfloat16(v.w - __bfloat162float(h3));
        dh[tid] = make_uint2(pack_bf2(h0, h1), pack_bf2(h2, h3));
        dl[tid] = make_uint2(pack_bf2(l0, l1), pack_bf2(l2, l3));
    } else {
        dh[tid] = make_uint2(0u, 0u);
        dl[tid] = make_uint2(0u, 0u);
    }
}

// ---------------------------------------------------------------------------
// Kernel: weight fp32 -> bf16 hi/lo split (which: 0 = w1, 1 = w2)
// ---------------------------------------------------------------------------
__global__ void convert_w_kernel(const float4* __restrict__ src, int which) {
    __nv_bfloat16* hi = which ? g_w2hi : g_w1hi;
    __nv_bfloat16* lo = which ? g_w2lo : g_w1lo;
    const size_t i = (size_t)blockIdx.x * 256 + threadIdx.x;
    float4 v = src[i];
    __nv_bfloat16 h0 = __float2bfloat16(v.x), h1 = __float2bfloat16(v.y);
    __nv_bfloat16 h2 = __float2bfloat16(v.z), h3 = __float2bfloat16(v.w);
    __nv_bfloat16 l0 = __float2bfloat16(v.x - __bfloat162float(h0));
    __nv_bfloat16 l1 = __float2bfloat16(v.y - __bfloat162float(h1));
    __nv_bfloat16 l2 = __float2bfloat16(v.z - __bfloat162float(h2));
    __nv_bfloat16 l3 = __float2bfloat16(v.w - __bfloat162float(h3));
    reinterpret_cast<uint2*>(hi)[i] = make_uint2(pack_bf2(h0, h1), pack_bf2(h2, h3));
    reinterpret_cast<uint2*>(lo)[i] = make_uint2(pack_bf2(l0, l1), pack_bf2(l2, l3));
}

// ---------------------------------------------------------------------------
// HMMA GEMM: Out[m,n] = act( sum_k A[m,k] * W[e,n,k] + bias[e,n] )
// BM=128, BN=128, BK=32, 8 warps (4x2), warp tile 32x64.
// bf16 3-way split: hi*hi + lo*hi + hi*lo, fp32 register accumulators.
// SMEM row layout: 128 rows x 128B; bytes [0,64)=hi k-chunk, [64,128)=lo.
// SW128 swizzle, cp.async double-buffered.
// ---------------------------------------------------------------------------
#define STAGE_BYTES 32768     // A 16KB + B 16KB
#define SMEM_TOTAL  (2 * STAGE_BYTES)

template<int KDIM, int NCOLS, bool GELU>
__global__ __launch_bounds__(256, 2)
void moe_hmma_kernel(const float* __restrict__ bias) {
    const int e = blockIdx.z;
    const int cnt = g_cnt[e];
    const int m0 = blockIdx.y * 128;
    if (m0 >= cnt) return;
    const int n0 = blockIdx.x * 128;
    const int row0 = g_off[e] + m0;
    const int tid = threadIdx.x;
    const int lane = tid & 31;
    const int wid = tid >> 5;
    const int wm = (wid & 3) * 32;     // warp M offset
    const int wn = (wid >> 2) * 64;    // warp N offset

    const __nv_bfloat16* __restrict__ Ahi = GELU ? g_xhi : g_hhi;
    const __nv_bfloat16* __restrict__ Alo = GELU ? g_xlo : g_hlo;
    const __nv_bfloat16* __restrict__ Whi = GELU ? g_w1hi : g_w2hi;
    const __nv_bfloat16* __restrict__ Wlo = GELU ? g_w1lo : g_w2lo;

    extern __shared__ char smem[];
    const uint32_t sb = smem_u32(smem);

    const size_t wrow0 = (size_t)e * NCOLS + n0;

    // each thread loads 4 chunks (16B) of A and 4 of B per stage
    const int lr = tid >> 1;                  // 0..127 (two threads per row)
    const int lc0 = (tid & 1) * 4;            // chunk 0..3 or 4..7

    auto load_stage = [&](int s, int k0) {
        const uint32_t st = sb + s * STAGE_BYTES;
#pragma unroll
        for (int c = 0; c < 4; c++) {
            const int ch = lc0 + c;                         // 0..7
            const int kk = k0 + (ch & 3) * 8;               // element offset
            const __nv_bfloat16* pa = (ch < 4) ? Ahi : Alo;
            const __nv_bfloat16* pb = (ch < 4) ? Whi : Wlo;
            cp16(st + swz(lr * 128 + ch * 16),
                 pa + (size_t)(row0 + lr) * KDIM + kk);
            cp16(st + 16384 + swz(lr * 128 + ch * 16),
                 pb + (wrow0 + lr) * KDIM + kk);
        }
        cp_commit();
    };

    float acc[2][8][4];
#pragma unroll
    for (int i = 0; i < 2; i++)
#pragma unroll
        for (int j = 0; j < 8; j++)
#pragma unroll
            for (int q = 0; q < 4; q++) acc[i][j][q] = 0.f;

    constexpr int ITERS = KDIM / 32;
    load_stage(0, 0);
    load_stage(1, 32);

    // ldmatrix lane address components (within-tile)
    const int a_row = (lane & 15);
    const int a_kb  = (lane >> 4) * 16;
    const int b_row = (lane & 7) + ((lane >> 4) * 8);      // q>>1 == lane>>4
    const int b_kb  = ((lane >> 3) & 1) * 16;

    for (int it = 0; it < ITERS; it++) {
        if (it < ITERS - 1) cp_wait<1>(); else cp_wait<0>();
        __syncthreads();

        const uint32_t Ab = sb + (it & 1) * STAGE_BYTES;
        const uint32_t Bb = Ab + 16384;

#pragma unroll
        for (int s = 0; s < 2; s++) {
            const int kb = s * 32;
            uint32_t ah[2][4], al[2][4], bf[8][2];
#pragma unroll
            for (int mt = 0; mt < 2; mt++) {
                const int r = wm + mt * 16 + a_row;
                ldm_x4(ah[mt], Ab + swz(r * 128 + kb + a_kb));
                ldm_x4(al[mt], Ab + swz(r * 128 + kb + a_kb + 64));
            }
            // B hi
#pragma unroll
            for (int p = 0; p < 4; p++) {
                const int r = wn + p * 16 + b_row;
                uint32_t t[4];
                ldm_x4(t, Bb + swz(r * 128 + kb + b_kb));
                bf[2 * p][0] = t[0]; bf[2 * p][1] = t[1];
                bf[2 * p + 1][0] = t[2]; bf[2 * p + 1][1] = t[3];
            }
#pragma unroll
            for (int mt = 0; mt < 2; mt++)
#pragma unroll
                for (int nt = 0; nt < 8; nt++)
                    mma_bf16(acc[mt][nt], ah[mt], bf[nt]);     // hi*hi
#pragma unroll
            for (int mt = 0; mt < 2; mt++)
#pragma unroll
                for (int nt = 0; nt < 8; nt++)
                    mma_bf16(acc[mt][nt], al[mt], bf[nt]);     // lo*hi
            // B lo
#pragma unroll
            for (int p = 0; p < 4; p++) {
                const int r = wn + p * 16 + b_row;
                uint32_t t[4];
                ldm_x4(t, Bb + swz(r * 128 + kb + b_kb + 64));
                bf[2 * p][0] = t[0]; bf[2 * p][1] = t[1];
                bf[2 * p + 1][0] = t[2]; bf[2 * p + 1][1] = t[3];
            }
#pragma unroll
            for (int mt = 0; mt < 2; mt++)
#pragma unroll
                for (int nt = 0; nt < 8; nt++)
                    mma_bf16(acc[mt][nt], ah[mt], bf[nt]);     // hi*lo
        }
        __syncthreads();
        if (it + 2 < ITERS) load_stage(it & 1, (it + 2) * 32);
    }

    // ---- epilogue ----
    const float* brow = bias + (size_t)e * NCOLS + n0;
#pragma unroll
    for (int mt = 0; mt < 2; mt++) {
#pragma unroll
        for (int nt = 0; nt < 8; nt++) {
            const int col = wn + nt * 8 + 2 * (lane & 3);
            const float b0 = brow[col], b1 = brow[col + 1];
#pragma unroll
            for (int h = 0; h < 2; h++) {
                const int gr = row0 + wm + mt * 16 + (lane >> 2) + h * 8;
                float v0 = acc[mt][nt][2 * h] + b0;
                float v1 = acc[mt][nt][2 * h + 1] + b1;
                const size_t o = (size_t)gr * NCOLS + n0 + col;
                if (GELU) {
                    v0 = 0.5f * v0 * (1.f + erff(v0 * 0.70710678118654752f));
                    v1 = 0.5f * v1 * (1.f + erff(v1 * 0.70710678118654752f));
                    __nv_bfloat16 h0 = __float2bfloat16(v0);
                    __nv_bfloat16 h1 = __float2bfloat16(v1);
                    __nv_bfloat16 l0 = __float2bfloat16(v0 - __bfloat162float(h0));
                    __nv_bfloat16 l1 = __float2bfloat16(v1 - __bfloat162float(h1));
                    *reinterpret_cast<uint32_t*>(g_hhi + o) = pack_bf2(h0, h1);
                    *reinterpret_cast<uint32_t*>(g_hlo + o) = pack_bf2(l0, l1);
                } else {
                    *reinterpret_cast<float2*>(g_y + o) = make_float2(v0, v1);
                }
            }
        }
    }
}

// ---------------------------------------------------------------------------
// Kernel: combine. out[n] = w0*y[row0] + w1*y[row1]
// ---------------------------------------------------------------------------
__global__ void combine_kernel(float* __restrict__ out) {
    const int idx = blockIdx.x * 256 + threadIdx.x;
    const int n = idx >> 8;
    const int d = (idx & 255) << 2;
    const int p0 = g_prow[2 * n], p1 = g_prow[2 * n + 1];
    const int r0 = g_off[p0 >> 12] + (p0 & (NTOK - 1));
    const int r1 = g_off[p1 >> 12] + (p1 & (NTOK - 1));
    const float w0 = g_pw[2 * n], w1 = g_pw[2 * n + 1];
    const float4 a = *reinterpret_cast<const float4*>(&g_y[(size_t)r0 * DDIM + d]);
    const float4 b = *reinterpret_cast<const float4*>(&g_y[(size_t)r1 * DDIM + d]);
    float4 o;
    o.x = w0 * a.x + w1 * b.x;
    o.y = w0 * a.y + w1 * b.y;
    o.z = w0 * a.z + w1 * b.z;
    o.w = w0 * a.w + w1 * b.w;
    *reinterpret_cast<float4*>(&out[(size_t)n * DDIM + d]) = o;
}

// ---------------------------------------------------------------------------
// Launch
// ---------------------------------------------------------------------------
extern "C" void kernel_launch(void* const* d_in, const int* in_sizes, int n_in,
                              void* d_out, int out_size) {
    const float* x      = (const float*)d_in[0];
    const float* gate_w = (const float*)d_in[1];
    const float* gate_b = (const float*)d_in[2];
    const float* w1     = (const float*)d_in[3];
    const float* b1     = (const float*)d_in[4];
    const float* w2     = (const float*)d_in[5];
    const float* b2     = (const float*)d_in[6];
    float* out = (float*)d_out;

    cudaFuncSetAttribute(moe_hmma_kernel<DDIM, IDIM, true>,
                         cudaFuncAttributeMaxDynamicSharedMemorySize, SMEM_TOTAL);
    cudaFuncSetAttribute(moe_hmma_kernel<IDIM, DDIM, false>,
                         cudaFuncAttributeMaxDynamicSharedMemorySize, SMEM_TOTAL);

    zero_cnt_kernel<<<1, 32>>>();
    routing_kernel<<<NTOK, 256>>>(x, gate_w, gate_b);
    offsets_kernel<<<1, 1>>>();
    gather_x_kernel<<<ROWCAP, 256>>>(x);

    convert_w_kernel<<<32768, 256>>>((const float4*)w1, 0);
    convert_w_kernel<<<32768, 256>>>((const float4*)w2, 1);

    // GEMM1: h = gelu(xg @ w1^T + b1); K=1024, N=4096
    dim3 g1(IDIM / 128, 32, NEXP);
    moe_hmma_kernel<DDIM, IDIM, true><<<g1, 256, SMEM_TOTAL>>>(b1);

    // GEMM2: y = h @ w2^T + b2; K=4096, N=1024
    dim3 g2(DDIM / 128, 32, NEXP);
    moe_hmma_kernel<IDIM, DDIM, false><<<g2, 256, SMEM_TOTAL>>>(b2);

    combine_kernel<<<(NTOK * DDIM / 4) / 256, 256>>>(out);
}

// round 4
// speedup vs baseline: 2.8681x; 1.5131x over previous
#include <cuda_runtime.h>
#include <cuda_fp16.h>
#include <math.h>
#include <stdint.h>

#define NTOK 4096
#define DDIM 1024
#define IDIM 4096
#define NEXP 8
#define ROWCAP 9216           // 8192 assignments + 8*128 padding

// ---------------------------------------------------------------------------
// Static scratch
// ---------------------------------------------------------------------------
__device__ int   g_cnt[NEXP];
__device__ int   g_off[NEXP + 1];
__device__ int   g_tok[NEXP * NTOK];
__device__ int   g_prow[NTOK * 2];
__device__ float g_pw[NTOK * 2];

__device__ __half g_xhi[(size_t)ROWCAP * DDIM];
__device__ __half g_xlo[(size_t)ROWCAP * DDIM];
__device__ __half g_w1[(size_t)NEXP * IDIM * DDIM];
__device__ __half g_w2[(size_t)NEXP * DDIM * IDIM];
__device__ __half g_hhi[(size_t)ROWCAP * IDIM];
__device__ __half g_hlo[(size_t)ROWCAP * IDIM];
__device__ float  g_y[(size_t)ROWCAP * DDIM];

// ---------------------------------------------------------------------------
// Helpers (base-target-safe PTX only)
// ---------------------------------------------------------------------------
__device__ __forceinline__ uint32_t smem_u32(const void* p) {
    uint32_t a;
    asm("{ .reg .u64 t; cvta.to.shared.u64 t, %1; cvt.u32.u64 %0, t; }" : "=r"(a) : "l"(p));
    return a;
}
__device__ __forceinline__ uint32_t swz(uint32_t o) { return o ^ ((o >> 3) & 0x70); }

__device__ __forceinline__ void cp16(uint32_t dst, const void* src) {
    asm volatile("cp.async.cg.shared.global [%0], [%1], 16;\n" :: "r"(dst), "l"(src) : "memory");
}
__device__ __forceinline__ void cp_commit() {
    asm volatile("cp.async.commit_group;\n" ::: "memory");
}
template<int N>
__device__ __forceinline__ void cp_wait() {
    asm volatile("cp.async.wait_group %0;\n" :: "n"(N) : "memory");
}
__device__ __forceinline__ void ldm_x4(uint32_t* r, uint32_t addr) {
    asm volatile("ldmatrix.sync.aligned.m8n8.x4.shared.b16 {%0,%1,%2,%3}, [%4];"
                 : "=r"(r[0]), "=r"(r[1]), "=r"(r[2]), "=r"(r[3]) : "r"(addr));
}
__device__ __forceinline__ void mma_f16(float* c, const uint32_t* a, const uint32_t* b) {
    asm volatile(
        "mma.sync.aligned.m16n8k16.row.col.f32.f16.f16.f32 "
        "{%0,%1,%2,%3}, {%4,%5,%6,%7}, {%8,%9}, {%0,%1,%2,%3};"
        : "+f"(c[0]), "+f"(c[1]), "+f"(c[2]), "+f"(c[3])
        : "r"(a[0]), "r"(a[1]), "r"(a[2]), "r"(a[3]), "r"(b[0]), "r"(b[1]));
}
__device__ __forceinline__ uint32_t pack_h2(__half a, __half b) {
    return ((uint32_t)__half_as_ushort(b) << 16) | (uint32_t)__half_as_ushort(a);
}

// ---------------------------------------------------------------------------
// Kernel: zero counters
// ---------------------------------------------------------------------------
__global__ void zero_cnt_kernel() {
    if (threadIdx.x < NEXP) g_cnt[threadIdx.x] = 0;
}

// ---------------------------------------------------------------------------
// Kernel: routing (one block per token)
// ---------------------------------------------------------------------------
__global__ void routing_kernel(const float* __restrict__ x,
                               const float* __restrict__ gw,
                               const float* __restrict__ gb) {
    const int n = blockIdx.x;
    const int tid = threadIdx.x;
    const float* xr = x + (size_t)n * DDIM;

    float acc[NEXP];
#pragma unroll
    for (int e = 0; e < NEXP; e++) acc[e] = 0.f;
    for (int d = tid; d < DDIM; d += 256) {
        const float xv = xr[d];
#pragma unroll
        for (int e = 0; e < NEXP; e++)
            acc[e] = fmaf(xv, gw[e * DDIM + d], acc[e]);
    }
    __shared__ float s[NEXP][256];
#pragma unroll
    for (int e = 0; e < NEXP; e++) s[e][tid] = acc[e];
    __syncthreads();
    for (int off = 128; off > 0; off >>= 1) {
        if (tid < off) {
#pragma unroll
            for (int e = 0; e < NEXP; e++) s[e][tid] += s[e][tid + off];
        }
        __syncthreads();
    }
    if (tid == 0) {
        float logits[NEXP];
#pragma unroll
        for (int e = 0; e < NEXP; e++) logits[e] = s[e][0] + gb[e];
        int i0 = 0; float v0 = logits[0];
#pragma unroll
        for (int e = 1; e < NEXP; e++)
            if (logits[e] > v0) { v0 = logits[e]; i0 = e; }
        int i1 = -1; float v1 = -INFINITY;
#pragma unroll
        for (int e = 0; e < NEXP; e++)
            if (e != i0 && logits[e] > v1) { v1 = logits[e]; i1 = e; }
        const float ew = expf(v1 - v0);
        const float inv = 1.f / (1.f + ew);
        int idx[2] = { i0, i1 };
        float ww[2] = { inv, ew * inv };
#pragma unroll
        for (int k = 0; k < 2; k++) {
            const int e = idx[k];
            const int slot = atomicAdd(&g_cnt[e], 1);
            g_tok[e * NTOK + slot] = n;
            g_prow[n * 2 + k] = e * NTOK + slot;
            g_pw[n * 2 + k] = ww[k];
        }
    }
}

// ---------------------------------------------------------------------------
// Kernel: 128-aligned exclusive prefix of counts
// ---------------------------------------------------------------------------
__global__ void offsets_kernel() {
    if (threadIdx.x == 0) {
        int o = 0;
        for (int e = 0; e < NEXP; e++) {
            g_off[e] = o;
            o += (g_cnt[e] + 127) & ~127;
        }
        g_off[NEXP] = o;
    }
}

// ---------------------------------------------------------------------------
// Kernel: gather token rows -> compacted layout, split fp32 -> fp16 hi/lo
// ---------------------------------------------------------------------------
__global__ void gather_x_kernel(const float* __restrict__ x) {
    const int row = blockIdx.x;
    const int tid = threadIdx.x;
    int e = -1, slot = 0;
#pragma unroll
    for (int i = 0; i < NEXP; i++) {
        if (row >= g_off[i] && row < g_off[i + 1]) { e = i; slot = row - g_off[i]; }
    }
    const bool valid = (e >= 0) && (slot < g_cnt[e]);
    uint2* dh = reinterpret_cast<uint2*>(g_xhi + (size_t)row * DDIM);
    uint2* dl = reinterpret_cast<uint2*>(g_xlo + (size_t)row * DDIM);
    if (valid) {
        const int token = g_tok[e * NTOK + slot];
        const float4* src = reinterpret_cast<const float4*>(x + (size_t)token * DDIM);
        float4 v = src[tid];
        __half h0 = __float2half_rn(v.x), h1 = __float2half_rn(v.y);
        __half h2 = __float2half_rn(v.z), h3 = __float2half_rn(v.w);
        __half l0 = __float2half_rn(v.x - __half2float(h0));
        __half l1 = __float2half_rn(v.y - __half2float(h1));
        __half l2 = __float2half_rn(v.z - __half2float(h2));
        __half l3 = __float2half_rn(v.w - __half2float(h3));
        dh[tid] = make_uint2(pack_h2(h0, h1), pack_h2(h2, h3));
        dl[tid] = make_uint2(pack_h2(l0, l1), pack_h2(l2, l3));
    } else {
        dh[tid] = make_uint2(0u, 0u);
        dl[tid] = make_uint2(0u, 0u);
    }
}

// ---------------------------------------------------------------------------
// Kernel: weight fp32 -> fp16 (single, round-to-nearest)
// ---------------------------------------------------------------------------
__global__ void convert_w_kernel(const float4* __restrict__ src, int which) {
    __half* dst = which ? g_w2 : g_w1;
    const size_t i = (size_t)blockIdx.x * 256 + threadIdx.x;
    float4 v = src[i];
    reinterpret_cast<uint2*>(dst)[i] =
        make_uint2(pack_h2(__float2half_rn(v.x), __float2half_rn(v.y)),
                   pack_h2(__float2half_rn(v.z), __float2half_rn(v.w)));
}

// ---------------------------------------------------------------------------
// HMMA GEMM: Out[m,n] = act( sum_k A[m,k] * W[e,n,k] + bias[e,n] )
// BM=128, BN=128, BK=32, 8 warps (4x2), warp tile 32x64.
// fp16 2-pass: A_hi*B + A_lo*B, B single fp16, fp32 accumulators.
// A smem: 128 rows x 128B (hi [0,64), lo [64,128)), SW128 swizzle.
// B smem: 64 rows x 128B; row r holds n=r in [0,64) and n=r+64 in [64,128).
// ---------------------------------------------------------------------------
#define STAGE_BYTES 24576     // A 16KB + B 8KB
#define SMEM_TOTAL  (2 * STAGE_BYTES)

template<int KDIM, int NCOLS, bool GELU>
__global__ __launch_bounds__(256, 2)
void moe_hmma_kernel(const float* __restrict__ bias) {
    const int e = blockIdx.z;
    const int cnt = g_cnt[e];
    const int m0 = blockIdx.y * 128;
    if (m0 >= cnt) return;
    const int n0 = blockIdx.x * 128;
    const int row0 = g_off[e] + m0;
    const int tid = threadIdx.x;
    const int lane = tid & 31;
    const int wid = tid >> 5;
    const int wm = (wid & 3) * 32;     // warp M offset
    const int wn = (wid >> 2) * 64;    // warp N offset

    const __half* __restrict__ Ahi = GELU ? g_xhi : g_hhi;
    const __half* __restrict__ Alo = GELU ? g_xlo : g_hlo;
    const __half* __restrict__ W   = GELU ? g_w1 : g_w2;

    extern __shared__ char smem[];
    const uint32_t sb = smem_u32(smem);

    const size_t wrow0 = (size_t)e * NCOLS + n0;

    // A loader: 1024 cp16 / 256 thr = 4 each. Two threads per row.
    const int lr = tid >> 1;               // 0..127
    const int lc0 = (tid & 1) * 4;         // chunks 0..3 (hi) or 4..7 (lo)
    // B loader: 512 cp16 / 256 thr = 2 each.

    auto load_stage = [&](int s, int k0) {
        const uint32_t st = sb + s * STAGE_BYTES;
#pragma unroll
        for (int c = 0; c < 4; c++) {
            const int ch = lc0 + c;                     // 0..7
            const int kk = k0 + (ch & 3) * 8;
            const __half* pa = (ch < 4) ? Ahi : Alo;
            cp16(st + swz(lr * 128 + ch * 16),
                 pa + (size_t)(row0 + lr) * KDIM + kk);
        }
#pragma unroll
        for (int i = 0; i < 2; i++) {
            const int idx = tid + i * 256;              // 0..511
            const int nn = idx >> 2;                    // 0..127
            const int c = idx & 3;                      // 16B chunk in 64B
            const uint32_t d = swz((nn & 63) * 128 + (nn >> 6) * 64 + c * 16);
            cp16(st + 16384 + d, W + (wrow0 + nn) * KDIM + k0 + c * 8);
        }
        cp_commit();
    };

    float acc[2][8][4];
#pragma unroll
    for (int i = 0; i < 2; i++)
#pragma unroll
        for (int j = 0; j < 8; j++)
#pragma unroll
            for (int q = 0; q < 4; q++) acc[i][j][q] = 0.f;

    constexpr int ITERS = KDIM / 32;
    load_stage(0, 0);
    load_stage(1, 32);

    const int a_row = (lane & 15);
    const int a_kb  = (lane >> 4) * 16;                 // 0 or 16 bytes
    const int b_row = (lane & 7) + ((lane >> 4) * 8);   // 0..15
    const int b_kb  = ((lane >> 3) & 1) * 16;           // 0 or 16 bytes

    for (int it = 0; it < ITERS; it++) {
        if (it < ITERS - 1) cp_wait<1>(); else cp_wait<0>();
        __syncthreads();

        const uint32_t Ab = sb + (it & 1) * STAGE_BYTES;
        const uint32_t Bb = Ab + 16384;

#pragma unroll
        for (int s = 0; s < 2; s++) {
            const int kbA = s * 32;                     // bytes within 64B k-chunk
            uint32_t ah[2][4], al[2][4], bf[8][2];
#pragma unroll
            for (int mt = 0; mt < 2; mt++) {
                const int r = wm + mt * 16 + a_row;
                ldm_x4(ah[mt], Ab + swz(r * 128 + kbA + a_kb));
                ldm_x4(al[mt], Ab + swz(r * 128 + kbA + a_kb + 64));
            }
#pragma unroll
            for (int p = 0; p < 4; p++) {
                const int nloc = wn + p * 16 + b_row;   // 0..127
                uint32_t t[4];
                ldm_x4(t, Bb + swz((nloc & 63) * 128 + (nloc >> 6) * 64 + kbA + b_kb));
                bf[2 * p][0] = t[0]; bf[2 * p][1] = t[1];
                bf[2 * p + 1][0] = t[2]; bf[2 * p + 1][1] = t[3];
            }
#pragma unroll
            for (int mt = 0; mt < 2; mt++)
#pragma unroll
                for (int nt = 0; nt < 8; nt++)
                    mma_f16(acc[mt][nt], ah[mt], bf[nt]);    // hi * W
#pragma unroll
            for (int mt = 0; mt < 2; mt++)
#pragma unroll
                for (int nt = 0; nt < 8; nt++)
                    mma_f16(acc[mt][nt], al[mt], bf[nt]);    // lo * W
        }
        __syncthreads();
        if (it + 2 < ITERS) load_stage(it & 1, (it + 2) * 32);
    }

    // ---- epilogue ----
    const float* brow = bias + (size_t)e * NCOLS + n0;
#pragma unroll
    for (int mt = 0; mt < 2; mt++) {
#pragma unroll
        for (int nt = 0; nt < 8; nt++) {
            const int col = wn + nt * 8 + 2 * (lane & 3);
            const float b0 = brow[col], b1 = brow[col + 1];
#pragma unroll
            for (int h = 0; h < 2; h++) {
                const int gr = row0 + wm + mt * 16 + (lane >> 2) + h * 8;
                float v0 = acc[mt][nt][2 * h] + b0;
                float v1 = acc[mt][nt][2 * h + 1] + b1;
                const size_t o = (size_t)gr * NCOLS + n0 + col;
                if (GELU) {
                    v0 = 0.5f * v0 * (1.f + erff(v0 * 0.70710678118654752f));
                    v1 = 0.5f * v1 * (1.f + erff(v1 * 0.70710678118654752f));
                    __half h0 = __float2half_rn(v0);
                    __half h1 = __float2half_rn(v1);
                    __half l0 = __float2half_rn(v0 - __half2float(h0));
                    __half l1 = __float2half_rn(v1 - __half2float(h1));
                    *reinterpret_cast<uint32_t*>(g_hhi + o) = pack_h2(h0, h1);
                    *reinterpret_cast<uint32_t*>(g_hlo + o) = pack_h2(l0, l1);
                } else {
                    *reinterpret_cast<float2*>(g_y + o) = make_float2(v0, v1);
                }
            }
        }
    }
}

// ---------------------------------------------------------------------------
// Kernel: combine. out[n] = w0*y[row0] + w1*y[row1]
// ---------------------------------------------------------------------------
__global__ void combine_kernel(float* __restrict__ out) {
    const int idx = blockIdx.x * 256 + threadIdx.x;
    const int n = idx >> 8;
    const int d = (idx & 255) << 2;
    const int p0 = g_prow[2 * n], p1 = g_prow[2 * n + 1];
    const int r0 = g_off[p0 >> 12] + (p0 & (NTOK - 1));
    const int r1 = g_off[p1 >> 12] + (p1 & (NTOK - 1));
    const float w0 = g_pw[2 * n], w1 = g_pw[2 * n + 1];
    const float4 a = *reinterpret_cast<const float4*>(&g_y[(size_t)r0 * DDIM + d]);
    const float4 b = *reinterpret_cast<const float4*>(&g_y[(size_t)r1 * DDIM + d]);
    float4 o;
    o.x = w0 * a.x + w1 * b.x;
    o.y = w0 * a.y + w1 * b.y;
    o.z = w0 * a.z + w1 * b.z;
    o.w = w0 * a.w + w1 * b.w;
    *reinterpret_cast<float4*>(&out[(size_t)n * DDIM + d]) = o;
}

// ---------------------------------------------------------------------------
// Launch
// ---------------------------------------------------------------------------
extern "C" void kernel_launch(void* const* d_in, const int* in_sizes, int n_in,
                              void* d_out, int out_size) {
    const float* x      = (const float*)d_in[0];
    const float* gate_w = (const float*)d_in[1];
    const float* gate_b = (const float*)d_in[2];
    const float* w1     = (const float*)d_in[3];
    const float* b1     = (const float*)d_in[4];
    const float* w2     = (const float*)d_in[5];
    const float* b2     = (const float*)d_in[6];
    float* out = (float*)d_out;

    cudaFuncSetAttribute(moe_hmma_kernel<DDIM, IDIM, true>,
                         cudaFuncAttributeMaxDynamicSharedMemorySize, SMEM_TOTAL);
    cudaFuncSetAttribute(moe_hmma_kernel<IDIM, DDIM, false>,
                         cudaFuncAttributeMaxDynamicSharedMemorySize, SMEM_TOTAL);

    zero_cnt_kernel<<<1, 32>>>();
    routing_kernel<<<NTOK, 256>>>(x, gate_w, gate_b);
    offsets_kernel<<<1, 1>>>();
    gather_x_kernel<<<ROWCAP, 256>>>(x);

    convert_w_kernel<<<32768, 256>>>((const float4*)w1, 0);
    convert_w_kernel<<<32768, 256>>>((const float4*)w2, 1);

    // GEMM1: h = gelu(xg @ w1^T + b1); K=1024, N=4096
    dim3 g1(IDIM / 128, 32, NEXP);
    moe_hmma_kernel<DDIM, IDIM, true><<<g1, 256, SMEM_TOTAL>>>(b1);

    // GEMM2: y = h @ w2^T + b2; K=4096, N=1024
    dim3 g2(DDIM / 128, 32, NEXP);
    moe_hmma_kernel<IDIM, DDIM, false><<<g2, 256, SMEM_TOTAL>>>(b2);

    combine_kernel<<<(NTOK * DDIM / 4) / 256, 256>>>(out);
}

// round 5
// speedup vs baseline: 6.9972x; 2.4397x over previous
#include <cuda_runtime.h>
#include <cuda_fp16.h>
#include <math.h>
#include <stdint.h>

#define NTOK 4096
#define DDIM 1024
#define IDIM 4096
#define NEXP 8
#define ROWCAP 9216           // 8192 assignments + 8*128 padding

// ---------------------------------------------------------------------------
// Static scratch
// ---------------------------------------------------------------------------
__device__ int   g_cnt[NEXP];
__device__ int   g_off[NEXP + 1];
__device__ int   g_tok[NEXP * NTOK];
__device__ int   g_prow[NTOK * 2];
__device__ float g_pw[NTOK * 2];

__device__ __half g_xh[(size_t)ROWCAP * DDIM];
__device__ __half g_w1[(size_t)NEXP * IDIM * DDIM];
__device__ __half g_w2[(size_t)NEXP * DDIM * IDIM];
__device__ __half g_h[(size_t)ROWCAP * IDIM];
__device__ float  g_y[(size_t)ROWCAP * DDIM];

// ---------------------------------------------------------------------------
// Helpers (base-target-safe PTX only)
// ---------------------------------------------------------------------------
__device__ __forceinline__ uint32_t smem_u32(const void* p) {
    uint32_t a;
    asm("{ .reg .u64 t; cvta.to.shared.u64 t, %1; cvt.u32.u64 %0, t; }" : "=r"(a) : "l"(p));
    return a;
}
__device__ __forceinline__ uint32_t swz(uint32_t o) { return o ^ ((o >> 3) & 0x70); }

__device__ __forceinline__ void cp16(uint32_t dst, const void* src) {
    asm volatile("cp.async.cg.shared.global [%0], [%1], 16;\n" :: "r"(dst), "l"(src) : "memory");
}
__device__ __forceinline__ void cp_commit() {
    asm volatile("cp.async.commit_group;\n" ::: "memory");
}
template<int N>
__device__ __forceinline__ void cp_wait() {
    asm volatile("cp.async.wait_group %0;\n" :: "n"(N) : "memory");
}
__device__ __forceinline__ void ldm_x4(uint32_t* r, uint32_t addr) {
    asm volatile("ldmatrix.sync.aligned.m8n8.x4.shared.b16 {%0,%1,%2,%3}, [%4];"
                 : "=r"(r[0]), "=r"(r[1]), "=r"(r[2]), "=r"(r[3]) : "r"(addr));
}
__device__ __forceinline__ void mma_f16(float* c, const uint32_t* a, const uint32_t* b) {
    asm volatile(
        "mma.sync.aligned.m16n8k16.row.col.f32.f16.f16.f32 "
        "{%0,%1,%2,%3}, {%4,%5,%6,%7}, {%8,%9}, {%0,%1,%2,%3};"
        : "+f"(c[0]), "+f"(c[1]), "+f"(c[2]), "+f"(c[3])
        : "r"(a[0]), "r"(a[1]), "r"(a[2]), "r"(a[3]), "r"(b[0]), "r"(b[1]));
}
__device__ __forceinline__ uint32_t pack_h2(__half a, __half b) {
    return ((uint32_t)__half_as_ushort(b) << 16) | (uint32_t)__half_as_ushort(a);
}

// ---------------------------------------------------------------------------
// Kernel: zero counters
// ---------------------------------------------------------------------------
__global__ void zero_cnt_kernel() {
    if (threadIdx.x < NEXP) g_cnt[threadIdx.x] = 0;
}

// ---------------------------------------------------------------------------
// Kernel: routing (one block per token)
// ---------------------------------------------------------------------------
__global__ void routing_kernel(const float* __restrict__ x,
                               const float* __restrict__ gw,
                               const float* __restrict__ gb) {
    const int n = blockIdx.x;
    const int tid = threadIdx.x;
    const float* xr = x + (size_t)n * DDIM;

    float acc[NEXP];
#pragma unroll
    for (int e = 0; e < NEXP; e++) acc[e] = 0.f;
    for (int d = tid; d < DDIM; d += 256) {
        const float xv = xr[d];
#pragma unroll
        for (int e = 0; e < NEXP; e++)
            acc[e] = fmaf(xv, gw[e * DDIM + d], acc[e]);
    }
    __shared__ float s[NEXP][256];
#pragma unroll
    for (int e = 0; e < NEXP; e++) s[e][tid] = acc[e];
    __syncthreads();
    for (int off = 128; off > 0; off >>= 1) {
        if (tid < off) {
#pragma unroll
            for (int e = 0; e < NEXP; e++) s[e][tid] += s[e][tid + off];
        }
        __syncthreads();
    }
    if (tid == 0) {
        float logits[NEXP];
#pragma unroll
        for (int e = 0; e < NEXP; e++) logits[e] = s[e][0] + gb[e];
        int i0 = 0; float v0 = logits[0];
#pragma unroll
        for (int e = 1; e < NEXP; e++)
            if (logits[e] > v0) { v0 = logits[e]; i0 = e; }
        int i1 = -1; float v1 = -INFINITY;
#pragma unroll
        for (int e = 0; e < NEXP; e++)
            if (e != i0 && logits[e] > v1) { v1 = logits[e]; i1 = e; }
        const float ew = expf(v1 - v0);
        const float inv = 1.f / (1.f + ew);
        int idx[2] = { i0, i1 };
        float ww[2] = { inv, ew * inv };
#pragma unroll
        for (int k = 0; k < 2; k++) {
            const int e = idx[k];
            const int slot = atomicAdd(&g_cnt[e], 1);
            g_tok[e * NTOK + slot] = n;
            g_prow[n * 2 + k] = e * NTOK + slot;
            g_pw[n * 2 + k] = ww[k];
        }
    }
}

// ---------------------------------------------------------------------------
// Kernel: 128-aligned exclusive prefix of counts
// ---------------------------------------------------------------------------
__global__ void offsets_kernel() {
    if (threadIdx.x == 0) {
        int o = 0;
        for (int e = 0; e < NEXP; e++) {
            g_off[e] = o;
            o += (g_cnt[e] + 127) & ~127;
        }
        g_off[NEXP] = o;
    }
}

// ---------------------------------------------------------------------------
// Kernel: gather token rows -> compacted fp16 layout
// ---------------------------------------------------------------------------
__global__ void gather_x_kernel(const float* __restrict__ x) {
    const int row = blockIdx.x;
    const int tid = threadIdx.x;
    int e = -1, slot = 0;
#pragma unroll
    for (int i = 0; i < NEXP; i++) {
        if (row >= g_off[i] && row < g_off[i + 1]) { e = i; slot = row - g_off[i]; }
    }
    const bool valid = (e >= 0) && (slot < g_cnt[e]);
    uint2* dh = reinterpret_cast<uint2*>(g_xh + (size_t)row * DDIM);
    if (valid) {
        const int token = g_tok[e * NTOK + slot];
        const float4* src = reinterpret_cast<const float4*>(x + (size_t)token * DDIM);
        float4 v = src[tid];
        dh[tid] = make_uint2(pack_h2(__float2half_rn(v.x), __float2half_rn(v.y)),
                             pack_h2(__float2half_rn(v.z), __float2half_rn(v.w)));
    } else {
        dh[tid] = make_uint2(0u, 0u);
    }
}

// ---------------------------------------------------------------------------
// Kernel: weight fp32 -> fp16
// ---------------------------------------------------------------------------
__global__ void convert_w_kernel(const float4* __restrict__ src, int which) {
    __half* dst = which ? g_w2 : g_w1;
    const size_t i = (size_t)blockIdx.x * 256 + threadIdx.x;
    float4 v = src[i];
    reinterpret_cast<uint2*>(dst)[i] =
        make_uint2(pack_h2(__float2half_rn(v.x), __float2half_rn(v.y)),
                   pack_h2(__float2half_rn(v.z), __float2half_rn(v.w)));
}

// ---------------------------------------------------------------------------
// HMMA GEMM: Out[m,n] = act( sum_k A[m,k] * W[e,n,k] + bias[e,n] )
// BM=128, BN=128, BK=32, 8 warps (4x2), warp tile 32x64, single fp16 pass.
// SMEM per stage: A 8KB + B 8KB; rows packed 2-per-128B (SW128 swizzled).
// 3-stage cp.async pipeline.
// ---------------------------------------------------------------------------
#define STAGE_BYTES 16384     // A 8KB + B 8KB
#define NSTAGE 3
#define SMEM_TOTAL  (NSTAGE * STAGE_BYTES)

template<int KDIM, int NCOLS, bool GELU>
__global__ __launch_bounds__(256, 2)
void moe_hmma_kernel(const float* __restrict__ bias) {
    const int e = blockIdx.z;
    const int cnt = g_cnt[e];
    const int m0 = blockIdx.y * 128;
    if (m0 >= cnt) return;
    const int n0 = blockIdx.x * 128;
    const int row0 = g_off[e] + m0;
    const int tid = threadIdx.x;
    const int lane = tid & 31;
    const int wid = tid >> 5;
    const int wm = (wid & 3) * 32;     // warp M offset
    const int wn = (wid >> 2) * 64;    // warp N offset

    const __half* __restrict__ A = GELU ? g_xh : g_h;
    const __half* __restrict__ W = GELU ? g_w1 : g_w2;

    extern __shared__ char smem[];
    const uint32_t sb = smem_u32(smem);

    const size_t wrow0 = (size_t)e * NCOLS + n0;

    // Loaders: A 512 cp16 + B 512 cp16 per stage, 4 per thread.
    auto load_stage = [&](int s, int k0) {
        const uint32_t st = sb + s * STAGE_BYTES;
#pragma unroll
        for (int i = 0; i < 2; i++) {
            const int idx = tid + i * 256;              // 0..511
            const int r = idx >> 2;                     // 0..127
            const int c = idx & 3;                      // 16B chunk within 64B
            const uint32_t d = swz((r & 63) * 128 + (r >> 6) * 64 + c * 16);
            cp16(st + d, A + (size_t)(row0 + r) * KDIM + k0 + c * 8);
            cp16(st + 8192 + d, W + (wrow0 + r) * KDIM + k0 + c * 8);
        }
        cp_commit();
    };

    float acc[2][8][4];
#pragma unroll
    for (int i = 0; i < 2; i++)
#pragma unroll
        for (int j = 0; j < 8; j++)
#pragma unroll
            for (int q = 0; q < 4; q++) acc[i][j][q] = 0.f;

    constexpr int ITERS = KDIM / 32;
    load_stage(0, 0);
    load_stage(1, 32);
    load_stage(2, 64);

    const int a_row = (lane & 15);
    const int a_kb  = (lane >> 4) * 16;                 // 0 or 16 bytes
    const int b_row = (lane & 7) + ((lane >> 4) * 8);   // 0..15
    const int b_kb  = ((lane >> 3) & 1) * 16;           // 0 or 16 bytes

    for (int it = 0; it < ITERS; it++) {
        // wait until stage (it % 3) is resident (tail-correct ladder)
        if (it <= ITERS - 3)      cp_wait<2>();
        else if (it == ITERS - 2) cp_wait<1>();
        else                      cp_wait<0>();
        __syncthreads();

        const uint32_t Ab = sb + (it % NSTAGE) * STAGE_BYTES;
        const uint32_t Bb = Ab + 8192;

#pragma unroll
        for (int s = 0; s < 2; s++) {
            const int kb = s * 32;                      // bytes within 64B k-chunk
            uint32_t af[2][4], bf[8][2];
#pragma unroll
            for (int mt = 0; mt < 2; mt++) {
                const int r = wm + mt * 16 + a_row;
                ldm_x4(af[mt], Ab + swz((r & 63) * 128 + (r >> 6) * 64 + kb + a_kb));
            }
#pragma unroll
            for (int p = 0; p < 4; p++) {
                const int nloc = wn + p * 16 + b_row;   // 0..127
                uint32_t t[4];
                ldm_x4(t, Bb + swz((nloc & 63) * 128 + (nloc >> 6) * 64 + kb + b_kb));
                bf[2 * p][0] = t[0]; bf[2 * p][1] = t[1];
                bf[2 * p + 1][0] = t[2]; bf[2 * p + 1][1] = t[3];
            }
#pragma unroll
            for (int mt = 0; mt < 2; mt++)
#pragma unroll
                for (int nt = 0; nt < 8; nt++)
                    mma_f16(acc[mt][nt], af[mt], bf[nt]);
        }
        __syncthreads();
        if (it + NSTAGE < ITERS) load_stage(it % NSTAGE, (it + NSTAGE) * 32);
    }

    // ---- epilogue ----
    const float* brow = bias + (size_t)e * NCOLS + n0;
#pragma unroll
    for (int mt = 0; mt < 2; mt++) {
#pragma unroll
        for (int nt = 0; nt < 8; nt++) {
            const int col = wn + nt * 8 + 2 * (lane & 3);
            const float b0 = brow[col], b1 = brow[col + 1];
#pragma unroll
            for (int h = 0; h < 2; h++) {
                const int gr = row0 + wm + mt * 16 + (lane >> 2) + h * 8;
                float v0 = acc[mt][nt][2 * h] + b0;
                float v1 = acc[mt][nt][2 * h + 1] + b1;
                const size_t o = (size_t)gr * NCOLS + n0 + col;
                if (GELU) {
                    v0 = 0.5f * v0 * (1.f + erff(v0 * 0.70710678118654752f));
                    v1 = 0.5f * v1 * (1.f + erff(v1 * 0.70710678118654752f));
                    *reinterpret_cast<uint32_t*>(g_h + o) =
                        pack_h2(__float2half_rn(v0), __float2half_rn(v1));
                } else {
                    *reinterpret_cast<float2*>(g_y + o) = make_float2(v0, v1);
                }
            }
        }
    }
}

// ---------------------------------------------------------------------------
// Kernel: combine. out[n] = w0*y[row0] + w1*y[row1]
// ---------------------------------------------------------------------------
__global__ void combine_kernel(float* __restrict__ out) {
    const int idx = blockIdx.x * 256 + threadIdx.x;
    const int n = idx >> 8;
    const int d = (idx & 255) << 2;
    const int p0 = g_prow[2 * n], p1 = g_prow[2 * n + 1];
    const int r0 = g_off[p0 >> 12] + (p0 & (NTOK - 1));
    const int r1 = g_off[p1 >> 12] + (p1 & (NTOK - 1));
    const float w0 = g_pw[2 * n], w1 = g_pw[2 * n + 1];
    const float4 a = *reinterpret_cast<const float4*>(&g_y[(size_t)r0 * DDIM + d]);
    const float4 b = *reinterpret_cast<const float4*>(&g_y[(size_t)r1 * DDIM + d]);
    float4 o;
    o.x = w0 * a.x + w1 * b.x;
    o.y = w0 * a.y + w1 * b.y;
    o.z = w0 * a.z + w1 * b.z;
    o.w = w0 * a.w + w1 * b.w;
    *reinterpret_cast<float4*>(&out[(size_t)n * DDIM + d]) = o;
}

// ---------------------------------------------------------------------------
// Launch
// ---------------------------------------------------------------------------
extern "C" void kernel_launch(void* const* d_in, const int* in_sizes, int n_in,
                              void* d_out, int out_size) {
    const float* x      = (const float*)d_in[0];
    const float* gate_w = (const float*)d_in[1];
    const float* gate_b = (const float*)d_in[2];
    const float* w1     = (const float*)d_in[3];
    const float* b1     = (const float*)d_in[4];
    const float* w2     = (const float*)d_in[5];
    const float* b2     = (const float*)d_in[6];
    float* out = (float*)d_out;

    cudaFuncSetAttribute(moe_hmma_kernel<DDIM, IDIM, true>,
                         cudaFuncAttributeMaxDynamicSharedMemorySize, SMEM_TOTAL);
    cudaFuncSetAttribute(moe_hmma_kernel<IDIM, DDIM, false>,
                         cudaFuncAttributeMaxDynamicSharedMemorySize, SMEM_TOTAL);

    zero_cnt_kernel<<<1, 32>>>();
    routing_kernel<<<NTOK, 256>>>(x, gate_w, gate_b);
    offsets_kernel<<<1, 1>>>();
    gather_x_kernel<<<ROWCAP, 256>>>(x);

    convert_w_kernel<<<32768, 256>>>((const float4*)w1, 0);
    convert_w_kernel<<<32768, 256>>>((const float4*)w2, 1);

    // GEMM1: h = gelu(xg @ w1^T + b1); K=1024, N=4096
    dim3 g1(IDIM / 128, 32, NEXP);
    moe_hmma_kernel<DDIM, IDIM, true><<<g1, 256, SMEM_TOTAL>>>(b1);

    // GEMM2: y = h @ w2^T + b2; K=4096, N=1024
    dim3 g2(DDIM / 128, 32, NEXP);
    moe_hmma_kernel<IDIM, DDIM, false><<<g2, 256, SMEM_TOTAL>>>(b2);

    combine_kernel<<<(NTOK * DDIM / 4) / 256, 256>>>(out);
}